// round 7
// baseline (speedup 1.0000x reference)
#include <cuda_runtime.h>
#include <cuda_bf16.h>
#include <cstddef>
#include <cstdint>

// Problem constants
#define Bc 2
#define Sc 2048
#define Dc 1024
#define Hc 16
#define DKc 64
#define FFc 4096
#define ROWS (Bc*Sc)          // 4096 flattened rows

// ---------------------------------------------------------------------------
// Scratch (static device allocations; no cudaMalloc allowed)
// ---------------------------------------------------------------------------
__device__ float g_q[ROWS*Dc];
__device__ float g_k[ROWS*Dc];
__device__ float g_v[ROWS*Dc];
__device__ float g_t[ROWS*Dc];    // attention out / ffn out
__device__ float g_x1[ROWS*Dc];
__device__ float g_x2[ROWS*Dc];
__device__ float g_h[ROWS*FFc];   // ffn hidden
__device__ float g_psum[4*Bc*Dc]; // seq-norm partial sums (4 seq splits)
__device__ float g_psq[4*Bc*Dc];

__device__ __forceinline__ void cp16(float* s, const float* g) {
    uint32_t sa = (uint32_t)__cvta_generic_to_shared(s);
    asm volatile("cp.async.cg.shared.global [%0], [%1], 16;" :: "r"(sa), "l"(g));
}
// ldmatrix x4: four 8x8 b16 tiles (= 8x4 tf32 tiles); lane supplies one row addr
__device__ __forceinline__ void ldsm4(uint32_t& r0, uint32_t& r1, uint32_t& r2,
                                      uint32_t& r3, const float* p) {
    uint32_t a = (uint32_t)__cvta_generic_to_shared(p);
    asm volatile("ldmatrix.sync.aligned.m8n8.x4.shared.b16 {%0,%1,%2,%3}, [%4];"
                 : "=r"(r0), "=r"(r1), "=r"(r2), "=r"(r3) : "r"(a));
}
// tf32 "fast path": raw fp32 bits, HW truncates mantissa (CUTLASS-style)
#define MMA_TF32(C, A0,A1,A2,A3, B0,B1)                                    \
    asm volatile(                                                          \
        "mma.sync.aligned.m16n8k8.row.col.f32.tf32.tf32.f32 "              \
        "{%0,%1,%2,%3}, {%4,%5,%6,%7}, {%8,%9}, {%0,%1,%2,%3};"            \
        : "+f"((C)[0]), "+f"((C)[1]), "+f"((C)[2]), "+f"((C)[3])           \
        : "r"(A0), "r"(A1), "r"(A2), "r"(A3), "r"(B0), "r"(B1))

// ---------------------------------------------------------------------------
// TF32 tensor-core GEMM: C[M,N] = A[M,K] @ B[K,N] + bias[N], optional ReLU
// Block tile 128x128, BK=32, 256 threads (8 warps, 2x4), warp tile 64x32.
// A-fragments via ldmatrix.x4 (4 LDSM/ks instead of 16 LDS); B scalar LDS.
// ---------------------------------------------------------------------------
#define AS_STRIDE 36
#define BS_STRIDE 136
#define AS_TILE (128*AS_STRIDE)
#define BS_TILE (32*BS_STRIDE)
#define GEMM_SMEM_BYTES ((2*AS_TILE + 2*BS_TILE)*4)   // 71680 B

__global__ __launch_bounds__(256)
void gemm_tf32(const float* __restrict__ A, const float* __restrict__ B,
               const float* __restrict__ bias, float* __restrict__ C,
               int M, int N, int K, int relu)
{
    extern __shared__ float smg[];
    float* As = smg;                    // [2][128][36]
    float* Bs = smg + 2*AS_TILE;        // [2][32][136]

    const int tid  = threadIdx.x;
    const int lane = tid & 31;
    const int wid  = tid >> 5;
    const int wm   = wid >> 2;
    const int wn   = wid & 3;
    const int grp  = lane >> 2;
    const int qid  = lane & 3;
    const int lrow = lane & 15;          // ldmatrix row within 16
    const int lcol = (lane >> 4) << 2;   // ldmatrix col offset (0 or 4 tf32)
    const int bm   = blockIdx.y * 128;
    const int bn   = blockIdx.x * 128;

    float c[4][4][4];
#pragma unroll
    for (int mt = 0; mt < 4; mt++)
#pragma unroll
        for (int nt = 0; nt < 4; nt++)
#pragma unroll
            for (int r = 0; r < 4; r++) c[mt][nt][r] = 0.f;

    const int T = K / 32;

    auto load_tile = [&](int t, int buf) {
        const float* Ag = A + (size_t)bm * K + t * 32;
        float* Ad = As + buf * AS_TILE;
#pragma unroll
        for (int i = 0; i < 4; i++) {
            int idx = tid + i * 256;
            int row = idx >> 3, q = idx & 7;
            cp16(Ad + row * AS_STRIDE + q * 4, Ag + (size_t)row * K + q * 4);
        }
        const float* Bg = B + (size_t)(t * 32) * N + bn;
        float* Bd = Bs + buf * BS_TILE;
#pragma unroll
        for (int i = 0; i < 4; i++) {
            int idx = tid + i * 256;
            int kr = idx >> 5, nq = idx & 31;
            cp16(Bd + kr * BS_STRIDE + nq * 4, Bg + (size_t)kr * N + nq * 4);
        }
    };

    load_tile(0, 0);
    asm volatile("cp.async.commit_group;" ::: "memory");

    for (int t = 0; t < T; t++) {
        asm volatile("cp.async.wait_group 0;" ::: "memory");
        __syncthreads();
        if (t + 1 < T) {
            load_tile(t + 1, (t + 1) & 1);
            asm volatile("cp.async.commit_group;" ::: "memory");
        }
        const float* Ab = As + (t & 1) * AS_TILE;
        const float* Bb = Bs + (t & 1) * BS_TILE;

#pragma unroll
        for (int ks = 0; ks < 4; ks++) {
            const int kb = ks * 8;
            uint32_t af[4][4], bf[4][2];
#pragma unroll
            for (int mt = 0; mt < 4; mt++)
                ldsm4(af[mt][0], af[mt][1], af[mt][2], af[mt][3],
                      Ab + (wm * 64 + mt * 16 + lrow) * AS_STRIDE + kb + lcol);
#pragma unroll
            for (int nt = 0; nt < 4; nt++) {
                const uint32_t* br = (const uint32_t*)
                    (Bb + (kb + qid) * BS_STRIDE + wn * 32 + nt * 8 + grp);
                bf[nt][0] = br[0];
                bf[nt][1] = br[4 * BS_STRIDE];
            }
#pragma unroll
            for (int mt = 0; mt < 4; mt++)
#pragma unroll
                for (int nt = 0; nt < 4; nt++)
                    MMA_TF32(c[mt][nt], af[mt][0], af[mt][1], af[mt][2], af[mt][3],
                             bf[nt][0], bf[nt][1]);
        }
        __syncthreads();
    }

#pragma unroll
    for (int mt = 0; mt < 4; mt++) {
        const int row = bm + wm * 64 + mt * 16 + grp;
#pragma unroll
        for (int nt = 0; nt < 4; nt++) {
            const int col = bn + wn * 32 + nt * 8 + qid * 2;
            const float b0 = bias[col], b1 = bias[col + 1];
            float v0 = c[mt][nt][0] + b0;
            float v1 = c[mt][nt][1] + b1;
            float v2 = c[mt][nt][2] + b0;
            float v3 = c[mt][nt][3] + b1;
            if (relu) {
                v0 = fmaxf(v0, 0.f); v1 = fmaxf(v1, 0.f);
                v2 = fmaxf(v2, 0.f); v3 = fmaxf(v3, 0.f);
            }
            C[(size_t)row * N + col]           = v0;
            C[(size_t)row * N + col + 1]       = v1;
            C[(size_t)(row + 8) * N + col]     = v2;
            C[(size_t)(row + 8) * N + col + 1] = v3;
        }
    }
}

// ---------------------------------------------------------------------------
// Flash attention with TF32 mma.sync tensor cores.
// Block = one (b,h) x 64 q rows. 4 warps; warp w owns q rows [w*16, w*16+16).
// Q fragments (scale folded) in registers; K-fragments via ldmatrix.x4
// (one LDSM serves two adjacent key-n tiles); V scalar; P via shfl remap.
// ---------------------------------------------------------------------------
#define FAS 68
#define FA_TILE (64*FAS)
struct FlashSmem {
    float Ks[2][FA_TILE];
    float Vs[2][FA_TILE];
};
#define FLASH_SMEM_BYTES ((int)sizeof(FlashSmem))   // 69632 B -> 3 blocks/SM

__global__ __launch_bounds__(128)
void flash_attn_mma(const float* __restrict__ Q, const float* __restrict__ K,
                    const float* __restrict__ V, float* __restrict__ O, int causal)
{
    extern __shared__ char smem_raw[];
    FlashSmem& sm = *reinterpret_cast<FlashSmem*>(smem_raw);

    const int q0 = blockIdx.x * 64;
    const int bh = blockIdx.y;
    const int b = bh >> 4;
    const int h = bh & 15;

    const int tid  = threadIdx.x;
    const int lane = tid & 31;
    const int w    = tid >> 5;       // warp 0..3
    const int g    = lane >> 2;      // 0..7
    const int q    = lane & 3;       // 0..3
    const int lrow = lane & 15;          // ldmatrix row within 16
    const int lcol4 = (lane >> 4) << 2;  // ldmatrix col offset (0/4)

    // ---- Q fragments in registers (scale 1/8 folded, raw bits) ----
    uint32_t qf[8][4];
    {
        const float* Qb = Q + ((size_t)(b * Sc + q0 + w * 16) * Dc) + h * DKc;
#pragma unroll
        for (int ks = 0; ks < 8; ks++) {
            const int kc = ks * 8 + q;
            qf[ks][0] = __float_as_uint(0.125f * Qb[(size_t)g * Dc + kc]);
            qf[ks][1] = __float_as_uint(0.125f * Qb[(size_t)(g + 8) * Dc + kc]);
            qf[ks][2] = __float_as_uint(0.125f * Qb[(size_t)g * Dc + kc + 4]);
            qf[ks][3] = __float_as_uint(0.125f * Qb[(size_t)(g + 8) * Dc + kc + 4]);
        }
    }

    float o[8][4];
#pragma unroll
    for (int nt = 0; nt < 8; nt++)
#pragma unroll
        for (int r = 0; r < 4; r++) o[nt][r] = 0.f;
    float m0 = -1e30f, m1 = -1e30f, l0 = 0.f, l1 = 0.f;

    const int row0 = q0 + w * 16 + g;       // global q row for c0/c1
    const int row1 = row0 + 8;              // for c2/c3

    auto load_kv = [&](int t, int buf) {
        const float* Kg = K + ((size_t)(b * Sc + t * 64) * Dc) + h * DKc;
        const float* Vg = V + ((size_t)(b * Sc + t * 64) * Dc) + h * DKc;
        float* Kd = sm.Ks[buf];
        float* Vd = sm.Vs[buf];
#pragma unroll
        for (int i = 0; i < 8; i++) {
            int idx = tid + i * 128;        // 0..1023
            int row = idx >> 4, c4 = idx & 15;
            cp16(Kd + row * FAS + c4 * 4, Kg + (size_t)row * Dc + c4 * 4);
            cp16(Vd + row * FAS + c4 * 4, Vg + (size_t)row * Dc + c4 * 4);
        }
    };

    const int ntiles = causal ? (q0 / 64 + 1) : (Sc / 64);
    load_kv(0, 0);
    asm volatile("cp.async.commit_group;" ::: "memory");

    // shfl source lanes for the P (C-frag -> A-frag) remap
    const int srcA = (lane & ~3) | (q >> 1);
    const int srcB = srcA + 2;
    const bool oddq = (q & 1);

    for (int t = 0; t < ntiles; t++) {
        asm volatile("cp.async.wait_group 0;" ::: "memory");
        __syncthreads();
        if (t + 1 < ntiles) {
            load_kv(t + 1, (t + 1) & 1);
            asm volatile("cp.async.commit_group;" ::: "memory");
        }
        const float* Kb = sm.Ks[t & 1];
        const float* Vb = sm.Vs[t & 1];
        const int k0 = t * 64;

        // ---- S = Q @ K^T  (K B-fragments via ldmatrix, 2 n-tiles per LDSM) ----
        float s[8][4];
#pragma unroll
        for (int nt = 0; nt < 8; nt++)
#pragma unroll
            for (int r = 0; r < 4; r++) s[nt][r] = 0.f;

#pragma unroll
        for (int ks = 0; ks < 8; ks++) {
            const int kc8 = ks * 8 + lcol4;
#pragma unroll
            for (int np = 0; np < 4; np++) {
                uint32_t b0e, b0o, b1e, b1o;
                ldsm4(b0e, b0o, b1e, b1o, Kb + (np * 16 + lrow) * FAS + kc8);
                MMA_TF32(s[2*np],   qf[ks][0], qf[ks][1], qf[ks][2], qf[ks][3], b0e, b1e);
                MMA_TF32(s[2*np+1], qf[ks][0], qf[ks][1], qf[ks][2], qf[ks][3], b0o, b1o);
            }
        }

        // ---- causal mask on diagonal tile ----
        if (causal && k0 == q0) {
#pragma unroll
            for (int nt = 0; nt < 8; nt++) {
                const int c = k0 + nt * 8 + 2 * q;
                if (c     > row0) s[nt][0] = -1e30f;
                if (c + 1 > row0) s[nt][1] = -1e30f;
                if (c     > row1) s[nt][2] = -1e30f;
                if (c + 1 > row1) s[nt][3] = -1e30f;
            }
        }

        // ---- online softmax (per-row state in registers) ----
        float t0 = -1e30f, t1 = -1e30f;
#pragma unroll
        for (int nt = 0; nt < 8; nt++) {
            t0 = fmaxf(t0, fmaxf(s[nt][0], s[nt][1]));
            t1 = fmaxf(t1, fmaxf(s[nt][2], s[nt][3]));
        }
        t0 = fmaxf(t0, __shfl_xor_sync(0xffffffffu, t0, 1));
        t0 = fmaxf(t0, __shfl_xor_sync(0xffffffffu, t0, 2));
        t1 = fmaxf(t1, __shfl_xor_sync(0xffffffffu, t1, 1));
        t1 = fmaxf(t1, __shfl_xor_sync(0xffffffffu, t1, 2));
        const float mn0 = fmaxf(m0, t0);
        const float mn1 = fmaxf(m1, t1);
        const float a0 = __expf(m0 - mn0);
        const float a1 = __expf(m1 - mn1);

        float sum0 = 0.f, sum1 = 0.f;
#pragma unroll
        for (int nt = 0; nt < 8; nt++) {
            float p0 = __expf(s[nt][0] - mn0);
            float p1 = __expf(s[nt][1] - mn0);
            float p2 = __expf(s[nt][2] - mn1);
            float p3 = __expf(s[nt][3] - mn1);
            s[nt][0] = p0; s[nt][1] = p1; s[nt][2] = p2; s[nt][3] = p3;
            sum0 += p0 + p1;
            sum1 += p2 + p3;
        }
        sum0 += __shfl_xor_sync(0xffffffffu, sum0, 1);
        sum0 += __shfl_xor_sync(0xffffffffu, sum0, 2);
        sum1 += __shfl_xor_sync(0xffffffffu, sum1, 1);
        sum1 += __shfl_xor_sync(0xffffffffu, sum1, 2);
        l0 = l0 * a0 + sum0;
        l1 = l1 * a1 + sum1;
        m0 = mn0; m1 = mn1;

#pragma unroll
        for (int nt = 0; nt < 8; nt++) {
            o[nt][0] *= a0; o[nt][1] *= a0;
            o[nt][2] *= a1; o[nt][3] *= a1;
        }

        // ---- O += P @ V  (P A-fragments built via shfl from C-fragments) ----
#pragma unroll
        for (int ks = 0; ks < 8; ks++) {
            float e0A = __shfl_sync(0xffffffffu, s[ks][0], srcA);
            float e1A = __shfl_sync(0xffffffffu, s[ks][1], srcA);
            float e2A = __shfl_sync(0xffffffffu, s[ks][2], srcA);
            float e3A = __shfl_sync(0xffffffffu, s[ks][3], srcA);
            float e0B = __shfl_sync(0xffffffffu, s[ks][0], srcB);
            float e1B = __shfl_sync(0xffffffffu, s[ks][1], srcB);
            float e2B = __shfl_sync(0xffffffffu, s[ks][2], srcB);
            float e3B = __shfl_sync(0xffffffffu, s[ks][3], srcB);
            uint32_t pa0 = __float_as_uint(oddq ? e1A : e0A);
            uint32_t pa1 = __float_as_uint(oddq ? e3A : e2A);
            uint32_t pa2 = __float_as_uint(oddq ? e1B : e0B);
            uint32_t pa3 = __float_as_uint(oddq ? e3B : e2B);

            const int kc = ks * 8 + q;
#pragma unroll
            for (int nt = 0; nt < 8; nt++) {
                const uint32_t* vr = (const uint32_t*)(Vb + kc * FAS + nt * 8 + g);
                MMA_TF32(o[nt], pa0, pa1, pa2, pa3, vr[0], vr[4 * FAS]);
            }
        }
        __syncthreads();
    }

    // ---- write O ----
    const float invl0 = 1.f / l0;
    const float invl1 = 1.f / l1;
    float* Ob0 = O + ((size_t)(b * Sc + row0) * Dc) + h * DKc;
    float* Ob1 = O + ((size_t)(b * Sc + row1) * Dc) + h * DKc;
#pragma unroll
    for (int nt = 0; nt < 8; nt++) {
        const int c = nt * 8 + 2 * q;
        *(float2*)&Ob0[c] = make_float2(o[nt][0] * invl0, o[nt][1] * invl0);
        *(float2*)&Ob1[c] = make_float2(o[nt][2] * invl1, o[nt][3] * invl1);
    }
}

// ---------------------------------------------------------------------------
// Seq-norm, split-K over the sequence dim (4 splits -> 256 blocks).
// Pass 1: y = a + b (stored), per-split column partial sums -> g_psum/g_psq.
// Pass 2: combine 4 partials, out = (y - mean) / unbiased_var, in place.
// Deterministic: fixed per-block slots, fixed combine order.
// ---------------------------------------------------------------------------
#define NZ 4
#define SZ (Sc/NZ)   // 512 rows per split

__global__ __launch_bounds__(1024)
void seqnorm_part(const float* __restrict__ a, const float* __restrict__ b,
                  float* __restrict__ y,
                  float* __restrict__ psum, float* __restrict__ psq)
{
    const int d  = blockIdx.x * 32 + threadIdx.x;
    const int bb = blockIdx.y;
    const int z  = blockIdx.z;
    const int ty = threadIdx.y;
    const size_t base = (size_t)bb * Sc * Dc + d;

    float sum = 0.f, sq = 0.f;
    for (int s = z * SZ + ty; s < (z + 1) * SZ; s += 32) {
        size_t off = base + (size_t)s * Dc;
        float v = a[off] + b[off];
        y[off] = v;
        sum += v;
        sq  += v * v;
    }

    __shared__ float ssum[32][33], ssq[32][33];
    ssum[ty][threadIdx.x] = sum;
    ssq[ty][threadIdx.x]  = sq;
    __syncthreads();

    if (ty == 0) {
        float S = 0.f, Q = 0.f;
        for (int i = 0; i < 32; i++) { S += ssum[i][threadIdx.x]; Q += ssq[i][threadIdx.x]; }
        const int slot = ((z * Bc) + bb) * Dc + d;
        psum[slot] = S;
        psq[slot]  = Q;
    }
}

__global__ __launch_bounds__(1024)
void seqnorm_apply(float* __restrict__ y,
                   const float* __restrict__ psum, const float* __restrict__ psq)
{
    const int d  = blockIdx.x * 32 + threadIdx.x;
    const int bb = blockIdx.y;
    const int z  = blockIdx.z;
    const int ty = threadIdx.y;
    const size_t base = (size_t)bb * Sc * Dc + d;

    __shared__ float smean[32], sinv[32];
    if (ty == 0) {
        float S = 0.f, Q = 0.f;
#pragma unroll
        for (int zz = 0; zz < NZ; zz++) {
            const int slot = ((zz * Bc) + bb) * Dc + d;
            S += psum[slot];
            Q += psq[slot];
        }
        float m   = S / (float)Sc;
        float var = (Q - (float)Sc * m * m) / (float)(Sc - 1);
        smean[threadIdx.x] = m;
        sinv[threadIdx.x]  = 1.f / var;
    }
    __syncthreads();

    const float m   = smean[threadIdx.x];
    const float inv = sinv[threadIdx.x];
    for (int s = z * SZ + ty; s < (z + 1) * SZ; s += 32) {
        size_t off = base + (size_t)s * Dc;
        y[off] = (y[off] - m) * inv;
    }
}

// ---------------------------------------------------------------------------
// Launch
// ---------------------------------------------------------------------------
extern "C" void kernel_launch(void* const* d_in, const int* in_sizes, int n_in,
                              void* d_out, int out_size)
{
    const float* dec = (const float*)d_in[0];
    const float* enc = (const float*)d_in[1];
    const float* Wq1 = (const float*)d_in[2];
    const float* Wk1 = (const float*)d_in[3];
    const float* Wv1 = (const float*)d_in[4];
    const float* bq1 = (const float*)d_in[5];
    const float* bk1 = (const float*)d_in[6];
    const float* bv1 = (const float*)d_in[7];
    const float* Wq2 = (const float*)d_in[8];
    const float* Wk2 = (const float*)d_in[9];
    const float* Wv2 = (const float*)d_in[10];
    const float* bq2 = (const float*)d_in[11];
    const float* bk2 = (const float*)d_in[12];
    const float* bv2 = (const float*)d_in[13];
    const float* W1  = (const float*)d_in[14];
    const float* b1  = (const float*)d_in[15];
    const float* W2  = (const float*)d_in[16];
    const float* b2  = (const float*)d_in[17];
    float* out = (float*)d_out;

    float *q, *k, *v, *t, *x1, *x2, *hbuf, *psum, *psq;
    cudaGetSymbolAddress((void**)&q,    g_q);
    cudaGetSymbolAddress((void**)&k,    g_k);
    cudaGetSymbolAddress((void**)&v,    g_v);
    cudaGetSymbolAddress((void**)&t,    g_t);
    cudaGetSymbolAddress((void**)&x1,   g_x1);
    cudaGetSymbolAddress((void**)&x2,   g_x2);
    cudaGetSymbolAddress((void**)&hbuf, g_h);
    cudaGetSymbolAddress((void**)&psum, g_psum);
    cudaGetSymbolAddress((void**)&psq,  g_psq);

    static bool attr_set = false;
    if (!attr_set) {
        cudaFuncSetAttribute(flash_attn_mma, cudaFuncAttributeMaxDynamicSharedMemorySize,
                             FLASH_SMEM_BYTES);
        cudaFuncSetAttribute(gemm_tf32, cudaFuncAttributeMaxDynamicSharedMemorySize,
                             GEMM_SMEM_BYTES);
        attr_set = true;
    }

    dim3 gemm_block(256);
    dim3 gproj(Dc / 128, ROWS / 128);     // (8, 32)
    dim3 gff1(FFc / 128, ROWS / 128);     // (32, 32)
    dim3 gff2(Dc / 128, ROWS / 128);

    dim3 fgrid(Sc / 64, Bc * Hc);         // (32, 32)
    dim3 fblock(128);

    dim3 ngrid(Dc / 32, Bc, NZ);          // (32, 2, 4) = 256 blocks
    dim3 nblock(32, 32);

    // ---- sublayer 1: causal self-attention ----
    gemm_tf32<<<gproj, gemm_block, GEMM_SMEM_BYTES>>>(dec, Wq1, bq1, q, ROWS, Dc, Dc, 0);
    gemm_tf32<<<gproj, gemm_block, GEMM_SMEM_BYTES>>>(dec, Wk1, bk1, k, ROWS, Dc, Dc, 0);
    gemm_tf32<<<gproj, gemm_block, GEMM_SMEM_BYTES>>>(dec, Wv1, bv1, v, ROWS, Dc, Dc, 0);
    flash_attn_mma<<<fgrid, fblock, FLASH_SMEM_BYTES>>>(q, k, v, t, 1);
    seqnorm_part<<<ngrid, nblock>>>(t, dec, x1, psum, psq);
    seqnorm_apply<<<ngrid, nblock>>>(x1, psum, psq);

    // ---- sublayer 2: cross-attention ----
    gemm_tf32<<<gproj, gemm_block, GEMM_SMEM_BYTES>>>(x1,  Wq2, bq2, q, ROWS, Dc, Dc, 0);
    gemm_tf32<<<gproj, gemm_block, GEMM_SMEM_BYTES>>>(enc, Wk2, bk2, k, ROWS, Dc, Dc, 0);
    gemm_tf32<<<gproj, gemm_block, GEMM_SMEM_BYTES>>>(enc, Wv2, bv2, v, ROWS, Dc, Dc, 0);
    flash_attn_mma<<<fgrid, fblock, FLASH_SMEM_BYTES>>>(q, k, v, t, 0);
    seqnorm_part<<<ngrid, nblock>>>(t, x1, x2, psum, psq);
    seqnorm_apply<<<ngrid, nblock>>>(x2, psum, psq);

    // ---- sublayer 3: FFN ----
    gemm_tf32<<<gff1, gemm_block, GEMM_SMEM_BYTES>>>(x2, W1, b1, hbuf, ROWS, FFc, Dc, 1);
    gemm_tf32<<<gff2, gemm_block, GEMM_SMEM_BYTES>>>(hbuf, W2, b2, t, ROWS, Dc, FFc, 0);
    seqnorm_part<<<ngrid, nblock>>>(t, x2, out, psum, psq);
    seqnorm_apply<<<ngrid, nblock>>>(out, psum, psq);
}

// round 10
// speedup vs baseline: 1.0156x; 1.0156x over previous
#include <cuda_runtime.h>
#include <cuda_bf16.h>
#include <cstddef>
#include <cstdint>

// Problem constants
#define Bc 2
#define Sc 2048
#define Dc 1024
#define Hc 16
#define DKc 64
#define FFc 4096
#define ROWS (Bc*Sc)          // 4096 flattened rows

// ---------------------------------------------------------------------------
// Scratch (static device allocations; no cudaMalloc allowed)
// ---------------------------------------------------------------------------
__device__ float g_q[ROWS*Dc];
__device__ float g_k[ROWS*Dc];
__device__ float g_v[ROWS*Dc];
__device__ float g_t[ROWS*Dc];    // attention out / ffn out
__device__ float g_x1[ROWS*Dc];
__device__ float g_x2[ROWS*Dc];
__device__ float g_h[ROWS*FFc];   // ffn hidden

__device__ __forceinline__ void cp16(float* s, const float* g) {
    uint32_t sa = (uint32_t)__cvta_generic_to_shared(s);
    asm volatile("cp.async.cg.shared.global [%0], [%1], 16;" :: "r"(sa), "l"(g));
}
// tf32 "fast path": raw fp32 bits, HW truncates mantissa (CUTLASS-style)
#define MMA_TF32(C, A0,A1,A2,A3, B0,B1)                                    \
    asm volatile(                                                          \
        "mma.sync.aligned.m16n8k8.row.col.f32.tf32.tf32.f32 "              \
        "{%0,%1,%2,%3}, {%4,%5,%6,%7}, {%8,%9}, {%0,%1,%2,%3};"            \
        : "+f"((C)[0]), "+f"((C)[1]), "+f"((C)[2]), "+f"((C)[3])           \
        : "r"(A0), "r"(A1), "r"(A2), "r"(A3), "r"(B0), "r"(B1))

// ---------------------------------------------------------------------------
// TF32 tensor-core GEMM: C[M,N] = A[M,K] @ B[K,N] + bias[N], optional ReLU
// Block tile 128x128, BK=32, 256 threads (8 warps, 2x4), warp tile 64x32.
// (R6 version — scalar LDS fragments; R7 ldmatrix variant was neutral.)
// ---------------------------------------------------------------------------
#define AS_STRIDE 36
#define BS_STRIDE 136
#define AS_TILE (128*AS_STRIDE)
#define BS_TILE (32*BS_STRIDE)
#define GEMM_SMEM_BYTES ((2*AS_TILE + 2*BS_TILE)*4)   // 71680 B

__global__ __launch_bounds__(256)
void gemm_tf32(const float* __restrict__ A, const float* __restrict__ B,
               const float* __restrict__ bias, float* __restrict__ C,
               int M, int N, int K, int relu)
{
    extern __shared__ float smg[];
    float* As = smg;                    // [2][128][36]
    float* Bs = smg + 2*AS_TILE;        // [2][32][136]

    const int tid  = threadIdx.x;
    const int lane = tid & 31;
    const int wid  = tid >> 5;
    const int wm   = wid >> 2;
    const int wn   = wid & 3;
    const int grp  = lane >> 2;
    const int qid  = lane & 3;
    const int bm   = blockIdx.y * 128;
    const int bn   = blockIdx.x * 128;

    float c[4][4][4];
#pragma unroll
    for (int mt = 0; mt < 4; mt++)
#pragma unroll
        for (int nt = 0; nt < 4; nt++)
#pragma unroll
            for (int r = 0; r < 4; r++) c[mt][nt][r] = 0.f;

    const int T = K / 32;

    auto load_tile = [&](int t, int buf) {
        const float* Ag = A + (size_t)bm * K + t * 32;
        float* Ad = As + buf * AS_TILE;
#pragma unroll
        for (int i = 0; i < 4; i++) {
            int idx = tid + i * 256;
            int row = idx >> 3, q = idx & 7;
            cp16(Ad + row * AS_STRIDE + q * 4, Ag + (size_t)row * K + q * 4);
        }
        const float* Bg = B + (size_t)(t * 32) * N + bn;
        float* Bd = Bs + buf * BS_TILE;
#pragma unroll
        for (int i = 0; i < 4; i++) {
            int idx = tid + i * 256;
            int kr = idx >> 5, nq = idx & 31;
            cp16(Bd + kr * BS_STRIDE + nq * 4, Bg + (size_t)kr * N + nq * 4);
        }
    };

    load_tile(0, 0);
    asm volatile("cp.async.commit_group;" ::: "memory");

    for (int t = 0; t < T; t++) {
        asm volatile("cp.async.wait_group 0;" ::: "memory");
        __syncthreads();
        if (t + 1 < T) {
            load_tile(t + 1, (t + 1) & 1);
            asm volatile("cp.async.commit_group;" ::: "memory");
        }
        const float* Ab = As + (t & 1) * AS_TILE;
        const float* Bb = Bs + (t & 1) * BS_TILE;

#pragma unroll
        for (int ks = 0; ks < 4; ks++) {
            const int kb = ks * 8;
            uint32_t af[4][4], bf[4][2];
#pragma unroll
            for (int mt = 0; mt < 4; mt++) {
                const uint32_t* ar = (const uint32_t*)
                    (Ab + (wm * 64 + mt * 16 + grp) * AS_STRIDE + kb + qid);
                af[mt][0] = ar[0];
                af[mt][1] = ar[8 * AS_STRIDE];
                af[mt][2] = ar[4];
                af[mt][3] = ar[8 * AS_STRIDE + 4];
            }
#pragma unroll
            for (int nt = 0; nt < 4; nt++) {
                const uint32_t* br = (const uint32_t*)
                    (Bb + (kb + qid) * BS_STRIDE + wn * 32 + nt * 8 + grp);
                bf[nt][0] = br[0];
                bf[nt][1] = br[4 * BS_STRIDE];
            }
#pragma unroll
            for (int mt = 0; mt < 4; mt++)
#pragma unroll
                for (int nt = 0; nt < 4; nt++)
                    MMA_TF32(c[mt][nt], af[mt][0], af[mt][1], af[mt][2], af[mt][3],
                             bf[nt][0], bf[nt][1]);
        }
        __syncthreads();
    }

#pragma unroll
    for (int mt = 0; mt < 4; mt++) {
        const int row = bm + wm * 64 + mt * 16 + grp;
#pragma unroll
        for (int nt = 0; nt < 4; nt++) {
            const int col = bn + wn * 32 + nt * 8 + qid * 2;
            const float b0 = bias[col], b1 = bias[col + 1];
            float v0 = c[mt][nt][0] + b0;
            float v1 = c[mt][nt][1] + b1;
            float v2 = c[mt][nt][2] + b0;
            float v3 = c[mt][nt][3] + b1;
            if (relu) {
                v0 = fmaxf(v0, 0.f); v1 = fmaxf(v1, 0.f);
                v2 = fmaxf(v2, 0.f); v3 = fmaxf(v3, 0.f);
            }
            C[(size_t)row * N + col]           = v0;
            C[(size_t)row * N + col + 1]       = v1;
            C[(size_t)(row + 8) * N + col]     = v2;
            C[(size_t)(row + 8) * N + col + 1] = v3;
        }
    }
}

// ---------------------------------------------------------------------------
// Flash attention with TF32 mma.sync tensor cores.
// Block = one (b,h) x 128 q rows. 8 warps (256 thr); warp w owns rows
// [w*16, w*16+16). K/V tiles (64 keys) shared by all 8 warps -> smem load
// traffic halved vs 64-row blocks, and 16 warps/SM instead of 12.
// Q fragments in registers; P via shfl remap (no smem round-trip).
// ---------------------------------------------------------------------------
#define FAS 68
#define FA_TILE (64*FAS)
struct FlashSmem {
    float Ks[2][FA_TILE];
    float Vs[2][FA_TILE];
};
#define FLASH_SMEM_BYTES ((int)sizeof(FlashSmem))   // 69632 B

__global__ __launch_bounds__(256)
void flash_attn_mma(const float* __restrict__ Q, const float* __restrict__ K,
                    const float* __restrict__ V, float* __restrict__ O, int causal)
{
    extern __shared__ char smem_raw[];
    FlashSmem& sm = *reinterpret_cast<FlashSmem*>(smem_raw);

    const int q0 = blockIdx.x * 128;
    const int bh = blockIdx.y;
    const int b = bh >> 4;
    const int h = bh & 15;

    const int tid  = threadIdx.x;
    const int lane = tid & 31;
    const int w    = tid >> 5;       // warp 0..7
    const int g    = lane >> 2;      // 0..7
    const int q    = lane & 3;       // 0..3

    // ---- Q fragments in registers (scale 1/8 folded, raw bits) ----
    uint32_t qf[8][4];
    {
        const float* Qb = Q + ((size_t)(b * Sc + q0 + w * 16) * Dc) + h * DKc;
#pragma unroll
        for (int ks = 0; ks < 8; ks++) {
            const int kc = ks * 8 + q;
            qf[ks][0] = __float_as_uint(0.125f * Qb[(size_t)g * Dc + kc]);
            qf[ks][1] = __float_as_uint(0.125f * Qb[(size_t)(g + 8) * Dc + kc]);
            qf[ks][2] = __float_as_uint(0.125f * Qb[(size_t)g * Dc + kc + 4]);
            qf[ks][3] = __float_as_uint(0.125f * Qb[(size_t)(g + 8) * Dc + kc + 4]);
        }
    }

    float o[8][4];
#pragma unroll
    for (int nt = 0; nt < 8; nt++)
#pragma unroll
        for (int r = 0; r < 4; r++) o[nt][r] = 0.f;
    float m0 = -1e30f, m1 = -1e30f, l0 = 0.f, l1 = 0.f;

    const int wrow = q0 + w * 16;           // warp's min q row
    const int row0 = wrow + g;              // global q row for c0/c1
    const int row1 = row0 + 8;              // for c2/c3

    auto load_kv = [&](int t, int buf) {
        const float* Kg = K + ((size_t)(b * Sc + t * 64) * Dc) + h * DKc;
        const float* Vg = V + ((size_t)(b * Sc + t * 64) * Dc) + h * DKc;
        float* Kd = sm.Ks[buf];
        float* Vd = sm.Vs[buf];
#pragma unroll
        for (int i = 0; i < 4; i++) {
            int idx = tid + i * 256;        // 0..1023
            int row = idx >> 4, c4 = idx & 15;
            cp16(Kd + row * FAS + c4 * 4, Kg + (size_t)row * Dc + c4 * 4);
            cp16(Vd + row * FAS + c4 * 4, Vg + (size_t)row * Dc + c4 * 4);
        }
    };

    const int ntiles = causal ? (q0 / 64 + 2) : (Sc / 64);
    load_kv(0, 0);
    asm volatile("cp.async.commit_group;" ::: "memory");

    // shfl source lanes for the P (C-frag -> A-frag) remap
    const int srcA = (lane & ~3) | (q >> 1);
    const int srcB = srcA + 2;
    const bool oddq = (q & 1);

    for (int t = 0; t < ntiles; t++) {
        asm volatile("cp.async.wait_group 0;" ::: "memory");
        __syncthreads();
        if (t + 1 < ntiles) {
            load_kv(t + 1, (t + 1) & 1);
            asm volatile("cp.async.commit_group;" ::: "memory");
        }
        const float* Kb = sm.Ks[t & 1];
        const float* Vb = sm.Vs[t & 1];
        const int k0 = t * 64;

        // ---- S = Q @ K^T ----
        float s[8][4];
#pragma unroll
        for (int nt = 0; nt < 8; nt++)
#pragma unroll
            for (int r = 0; r < 4; r++) s[nt][r] = 0.f;

#pragma unroll
        for (int ks = 0; ks < 8; ks++) {
            const int kc = ks * 8 + q;
#pragma unroll
            for (int nt = 0; nt < 8; nt++) {
                const uint32_t* kr = (const uint32_t*)(Kb + (nt * 8 + g) * FAS + kc);
                MMA_TF32(s[nt], qf[ks][0], qf[ks][1], qf[ks][2], qf[ks][3],
                         kr[0], kr[4]);
            }
        }

        // ---- causal mask: any tile reaching past this warp's min row ----
        if (causal && (k0 + 63 > wrow)) {
#pragma unroll
            for (int nt = 0; nt < 8; nt++) {
                const int c = k0 + nt * 8 + 2 * q;
                if (c     > row0) s[nt][0] = -1e30f;
                if (c + 1 > row0) s[nt][1] = -1e30f;
                if (c     > row1) s[nt][2] = -1e30f;
                if (c + 1 > row1) s[nt][3] = -1e30f;
            }
        }

        // ---- online softmax (per-row state in registers) ----
        float t0 = -1e30f, t1 = -1e30f;
#pragma unroll
        for (int nt = 0; nt < 8; nt++) {
            t0 = fmaxf(t0, fmaxf(s[nt][0], s[nt][1]));
            t1 = fmaxf(t1, fmaxf(s[nt][2], s[nt][3]));
        }
        t0 = fmaxf(t0, __shfl_xor_sync(0xffffffffu, t0, 1));
        t0 = fmaxf(t0, __shfl_xor_sync(0xffffffffu, t0, 2));
        t1 = fmaxf(t1, __shfl_xor_sync(0xffffffffu, t1, 1));
        t1 = fmaxf(t1, __shfl_xor_sync(0xffffffffu, t1, 2));
        const float mn0 = fmaxf(m0, t0);
        const float mn1 = fmaxf(m1, t1);
        const float a0 = __expf(m0 - mn0);
        const float a1 = __expf(m1 - mn1);

        float sum0 = 0.f, sum1 = 0.f;
#pragma unroll
        for (int nt = 0; nt < 8; nt++) {
            float p0 = __expf(s[nt][0] - mn0);
            float p1 = __expf(s[nt][1] - mn0);
            float p2 = __expf(s[nt][2] - mn1);
            float p3 = __expf(s[nt][3] - mn1);
            s[nt][0] = p0; s[nt][1] = p1; s[nt][2] = p2; s[nt][3] = p3;
            sum0 += p0 + p1;
            sum1 += p2 + p3;
        }
        sum0 += __shfl_xor_sync(0xffffffffu, sum0, 1);
        sum0 += __shfl_xor_sync(0xffffffffu, sum0, 2);
        sum1 += __shfl_xor_sync(0xffffffffu, sum1, 1);
        sum1 += __shfl_xor_sync(0xffffffffu, sum1, 2);
        l0 = l0 * a0 + sum0;
        l1 = l1 * a1 + sum1;
        m0 = mn0; m1 = mn1;

#pragma unroll
        for (int nt = 0; nt < 8; nt++) {
            o[nt][0] *= a0; o[nt][1] *= a0;
            o[nt][2] *= a1; o[nt][3] *= a1;
        }

        // ---- O += P @ V  (P A-fragments built via shfl from C-fragments) ----
#pragma unroll
        for (int ks = 0; ks < 8; ks++) {
            float e0A = __shfl_sync(0xffffffffu, s[ks][0], srcA);
            float e1A = __shfl_sync(0xffffffffu, s[ks][1], srcA);
            float e2A = __shfl_sync(0xffffffffu, s[ks][2], srcA);
            float e3A = __shfl_sync(0xffffffffu, s[ks][3], srcA);
            float e0B = __shfl_sync(0xffffffffu, s[ks][0], srcB);
            float e1B = __shfl_sync(0xffffffffu, s[ks][1], srcB);
            float e2B = __shfl_sync(0xffffffffu, s[ks][2], srcB);
            float e3B = __shfl_sync(0xffffffffu, s[ks][3], srcB);
            uint32_t pa0 = __float_as_uint(oddq ? e1A : e0A);
            uint32_t pa1 = __float_as_uint(oddq ? e3A : e2A);
            uint32_t pa2 = __float_as_uint(oddq ? e1B : e0B);
            uint32_t pa3 = __float_as_uint(oddq ? e3B : e2B);

            const int kc = ks * 8 + q;
#pragma unroll
            for (int nt = 0; nt < 8; nt++) {
                const uint32_t* vr = (const uint32_t*)(Vb + kc * FAS + nt * 8 + g);
                MMA_TF32(o[nt], pa0, pa1, pa2, pa3, vr[0], vr[4 * FAS]);
            }
        }
        __syncthreads();
    }

    // ---- write O ----
    const float invl0 = 1.f / l0;
    const float invl1 = 1.f / l1;
    float* Ob0 = O + ((size_t)(b * Sc + row0) * Dc) + h * DKc;
    float* Ob1 = O + ((size_t)(b * Sc + row1) * Dc) + h * DKc;
#pragma unroll
    for (int nt = 0; nt < 8; nt++) {
        const int c = nt * 8 + 2 * q;
        *(float2*)&Ob0[c] = make_float2(o[nt][0] * invl0, o[nt][1] * invl0);
        *(float2*)&Ob1[c] = make_float2(o[nt][2] * invl1, o[nt][3] * invl1);
    }
}

// ---------------------------------------------------------------------------
// y = a + b, then normalize over the SEQUENCE dim: (y - mean) / unbiased_var
// (R6 fused version — the R7 split-K variant regressed on launch overhead.)
// ---------------------------------------------------------------------------
__global__ __launch_bounds__(1024)
void add_seqnorm(const float* __restrict__ a, const float* __restrict__ b,
                 float* __restrict__ out)
{
    const int d  = blockIdx.x * 32 + threadIdx.x;
    const int bb = blockIdx.y;
    const int ty = threadIdx.y;
    const size_t base = (size_t)bb * Sc * Dc + d;

    float sum = 0.f, sq = 0.f;
    for (int s = ty; s < Sc; s += 32) {
        size_t off = base + (size_t)s * Dc;
        float y = a[off] + b[off];
        out[off] = y;
        sum += y;
        sq  += y * y;
    }

    __shared__ float ssum[32][33], ssq[32][33];
    ssum[ty][threadIdx.x] = sum;
    ssq[ty][threadIdx.x]  = sq;
    __syncthreads();

    __shared__ float smean[32], sinv[32];
    if (ty == 0) {
        float S = 0.f, Q = 0.f;
        for (int i = 0; i < 32; i++) { S += ssum[i][threadIdx.x]; Q += ssq[i][threadIdx.x]; }
        float m   = S / (float)Sc;
        float var = (Q - (float)Sc * m * m) / (float)(Sc - 1);
        smean[threadIdx.x] = m;
        sinv[threadIdx.x]  = 1.f / var;
    }
    __syncthreads();

    const float m   = smean[threadIdx.x];
    const float inv = sinv[threadIdx.x];
    for (int s = ty; s < Sc; s += 32) {
        size_t off = base + (size_t)s * Dc;
        out[off] = (out[off] - m) * inv;
    }
}

// ---------------------------------------------------------------------------
// Launch
// ---------------------------------------------------------------------------
extern "C" void kernel_launch(void* const* d_in, const int* in_sizes, int n_in,
                              void* d_out, int out_size)
{
    const float* dec = (const float*)d_in[0];
    const float* enc = (const float*)d_in[1];
    const float* Wq1 = (const float*)d_in[2];
    const float* Wk1 = (const float*)d_in[3];
    const float* Wv1 = (const float*)d_in[4];
    const float* bq1 = (const float*)d_in[5];
    const float* bk1 = (const float*)d_in[6];
    const float* bv1 = (const float*)d_in[7];
    const float* Wq2 = (const float*)d_in[8];
    const float* Wk2 = (const float*)d_in[9];
    const float* Wv2 = (const float*)d_in[10];
    const float* bq2 = (const float*)d_in[11];
    const float* bk2 = (const float*)d_in[12];
    const float* bv2 = (const float*)d_in[13];
    const float* W1  = (const float*)d_in[14];
    const float* b1  = (const float*)d_in[15];
    const float* W2  = (const float*)d_in[16];
    const float* b2  = (const float*)d_in[17];
    float* out = (float*)d_out;

    float *q, *k, *v, *t, *x1, *x2, *hbuf;
    cudaGetSymbolAddress((void**)&q,    g_q);
    cudaGetSymbolAddress((void**)&k,    g_k);
    cudaGetSymbolAddress((void**)&v,    g_v);
    cudaGetSymbolAddress((void**)&t,    g_t);
    cudaGetSymbolAddress((void**)&x1,   g_x1);
    cudaGetSymbolAddress((void**)&x2,   g_x2);
    cudaGetSymbolAddress((void**)&hbuf, g_h);

    static bool attr_set = false;
    if (!attr_set) {
        cudaFuncSetAttribute(flash_attn_mma, cudaFuncAttributeMaxDynamicSharedMemorySize,
                             FLASH_SMEM_BYTES);
        cudaFuncSetAttribute(gemm_tf32, cudaFuncAttributeMaxDynamicSharedMemorySize,
                             GEMM_SMEM_BYTES);
        attr_set = true;
    }

    dim3 gemm_block(256);
    dim3 gproj(Dc / 128, ROWS / 128);     // (8, 32)
    dim3 gff1(FFc / 128, ROWS / 128);     // (32, 32)
    dim3 gff2(Dc / 128, ROWS / 128);

    dim3 fgrid(Sc / 128, Bc * Hc);        // (16, 32) = 512 blocks
    dim3 fblock(256);

    dim3 ngrid(Dc / 32, Bc);              // (32, 2)
    dim3 nblock(32, 32);

    // ---- sublayer 1: causal self-attention ----
    gemm_tf32<<<gproj, gemm_block, GEMM_SMEM_BYTES>>>(dec, Wq1, bq1, q, ROWS, Dc, Dc, 0);
    gemm_tf32<<<gproj, gemm_block, GEMM_SMEM_BYTES>>>(dec, Wk1, bk1, k, ROWS, Dc, Dc, 0);
    gemm_tf32<<<gproj, gemm_block, GEMM_SMEM_BYTES>>>(dec, Wv1, bv1, v, ROWS, Dc, Dc, 0);
    flash_attn_mma<<<fgrid, fblock, FLASH_SMEM_BYTES>>>(q, k, v, t, 1);
    add_seqnorm<<<ngrid, nblock>>>(t, dec, x1);

    // ---- sublayer 2: cross-attention ----
    gemm_tf32<<<gproj, gemm_block, GEMM_SMEM_BYTES>>>(x1,  Wq2, bq2, q, ROWS, Dc, Dc, 0);
    gemm_tf32<<<gproj, gemm_block, GEMM_SMEM_BYTES>>>(enc, Wk2, bk2, k, ROWS, Dc, Dc, 0);
    gemm_tf32<<<gproj, gemm_block, GEMM_SMEM_BYTES>>>(enc, Wv2, bv2, v, ROWS, Dc, Dc, 0);
    flash_attn_mma<<<fgrid, fblock, FLASH_SMEM_BYTES>>>(q, k, v, t, 0);
    add_seqnorm<<<ngrid, nblock>>>(t, x1, x2);

    // ---- sublayer 3: FFN ----
    gemm_tf32<<<gff1, gemm_block, GEMM_SMEM_BYTES>>>(x2, W1, b1, hbuf, ROWS, FFc, Dc, 1);
    gemm_tf32<<<gff2, gemm_block, GEMM_SMEM_BYTES>>>(hbuf, W2, b2, t, ROWS, Dc, FFc, 0);
    add_seqnorm<<<ngrid, nblock>>>(t, x2, out);
}

// round 11
// speedup vs baseline: 1.0672x; 1.0509x over previous
#include <cuda_runtime.h>
#include <cuda_bf16.h>
#include <cstddef>
#include <cstdint>

// Problem constants
#define Bc 2
#define Sc 2048
#define Dc 1024
#define Hc 16
#define DKc 64
#define FFc 4096
#define ROWS (Bc*Sc)          // 4096 flattened rows

// ---------------------------------------------------------------------------
// Scratch (static device allocations; no cudaMalloc allowed)
// ---------------------------------------------------------------------------
__device__ float g_q[ROWS*Dc];
__device__ float g_k[ROWS*Dc];
__device__ float g_v[ROWS*Dc];
__device__ float g_t[ROWS*Dc];    // attention out / ffn out
__device__ float g_x1[ROWS*Dc];
__device__ float g_x2[ROWS*Dc];
__device__ float g_h[ROWS*FFc];   // ffn hidden

__device__ __forceinline__ void cp16(float* s, const float* g) {
    uint32_t sa = (uint32_t)__cvta_generic_to_shared(s);
    asm volatile("cp.async.cg.shared.global [%0], [%1], 16;" :: "r"(sa), "l"(g));
}
// tf32 "fast path": raw fp32 bits, HW truncates mantissa (CUTLASS-style)
#define MMA_TF32(C, A0,A1,A2,A3, B0,B1)                                    \
    asm volatile(                                                          \
        "mma.sync.aligned.m16n8k8.row.col.f32.tf32.tf32.f32 "              \
        "{%0,%1,%2,%3}, {%4,%5,%6,%7}, {%8,%9}, {%0,%1,%2,%3};"            \
        : "+f"((C)[0]), "+f"((C)[1]), "+f"((C)[2]), "+f"((C)[3])           \
        : "r"(A0), "r"(A1), "r"(A2), "r"(A3), "r"(B0), "r"(B1))

// ---------------------------------------------------------------------------
// TF32 tensor-core GEMM: C[M,N] = A[M,K] @ B[K,N] + bias[N], optional ReLU
// Block tile 128x128, BK=32, 256 threads (8 warps, 2x4), warp tile 64x32.
// (R6 version.)
// ---------------------------------------------------------------------------
#define AS_STRIDE 36
#define BS_STRIDE 136
#define AS_TILE (128*AS_STRIDE)
#define BS_TILE (32*BS_STRIDE)
#define GEMM_SMEM_BYTES ((2*AS_TILE + 2*BS_TILE)*4)   // 71680 B

__global__ __launch_bounds__(256)
void gemm_tf32(const float* __restrict__ A, const float* __restrict__ B,
               const float* __restrict__ bias, float* __restrict__ C,
               int M, int N, int K, int relu)
{
    extern __shared__ float smg[];
    float* As = smg;                    // [2][128][36]
    float* Bs = smg + 2*AS_TILE;        // [2][32][136]

    const int tid  = threadIdx.x;
    const int lane = tid & 31;
    const int wid  = tid >> 5;
    const int wm   = wid >> 2;
    const int wn   = wid & 3;
    const int grp  = lane >> 2;
    const int qid  = lane & 3;
    const int bm   = blockIdx.y * 128;
    const int bn   = blockIdx.x * 128;

    float c[4][4][4];
#pragma unroll
    for (int mt = 0; mt < 4; mt++)
#pragma unroll
        for (int nt = 0; nt < 4; nt++)
#pragma unroll
            for (int r = 0; r < 4; r++) c[mt][nt][r] = 0.f;

    const int T = K / 32;

    auto load_tile = [&](int t, int buf) {
        const float* Ag = A + (size_t)bm * K + t * 32;
        float* Ad = As + buf * AS_TILE;
#pragma unroll
        for (int i = 0; i < 4; i++) {
            int idx = tid + i * 256;
            int row = idx >> 3, q = idx & 7;
            cp16(Ad + row * AS_STRIDE + q * 4, Ag + (size_t)row * K + q * 4);
        }
        const float* Bg = B + (size_t)(t * 32) * N + bn;
        float* Bd = Bs + buf * BS_TILE;
#pragma unroll
        for (int i = 0; i < 4; i++) {
            int idx = tid + i * 256;
            int kr = idx >> 5, nq = idx & 31;
            cp16(Bd + kr * BS_STRIDE + nq * 4, Bg + (size_t)kr * N + nq * 4);
        }
    };

    load_tile(0, 0);
    asm volatile("cp.async.commit_group;" ::: "memory");

    for (int t = 0; t < T; t++) {
        asm volatile("cp.async.wait_group 0;" ::: "memory");
        __syncthreads();
        if (t + 1 < T) {
            load_tile(t + 1, (t + 1) & 1);
            asm volatile("cp.async.commit_group;" ::: "memory");
        }
        const float* Ab = As + (t & 1) * AS_TILE;
        const float* Bb = Bs + (t & 1) * BS_TILE;

#pragma unroll
        for (int ks = 0; ks < 4; ks++) {
            const int kb = ks * 8;
            uint32_t af[4][4], bf[4][2];
#pragma unroll
            for (int mt = 0; mt < 4; mt++) {
                const uint32_t* ar = (const uint32_t*)
                    (Ab + (wm * 64 + mt * 16 + grp) * AS_STRIDE + kb + qid);
                af[mt][0] = ar[0];
                af[mt][1] = ar[8 * AS_STRIDE];
                af[mt][2] = ar[4];
                af[mt][3] = ar[8 * AS_STRIDE + 4];
            }
#pragma unroll
            for (int nt = 0; nt < 4; nt++) {
                const uint32_t* br = (const uint32_t*)
                    (Bb + (kb + qid) * BS_STRIDE + wn * 32 + nt * 8 + grp);
                bf[nt][0] = br[0];
                bf[nt][1] = br[4 * BS_STRIDE];
            }
#pragma unroll
            for (int mt = 0; mt < 4; mt++)
#pragma unroll
                for (int nt = 0; nt < 4; nt++)
                    MMA_TF32(c[mt][nt], af[mt][0], af[mt][1], af[mt][2], af[mt][3],
                             bf[nt][0], bf[nt][1]);
        }
        __syncthreads();
    }

#pragma unroll
    for (int mt = 0; mt < 4; mt++) {
        const int row = bm + wm * 64 + mt * 16 + grp;
#pragma unroll
        for (int nt = 0; nt < 4; nt++) {
            const int col = bn + wn * 32 + nt * 8 + qid * 2;
            const float b0 = bias[col], b1 = bias[col + 1];
            float v0 = c[mt][nt][0] + b0;
            float v1 = c[mt][nt][1] + b1;
            float v2 = c[mt][nt][2] + b0;
            float v3 = c[mt][nt][3] + b1;
            if (relu) {
                v0 = fmaxf(v0, 0.f); v1 = fmaxf(v1, 0.f);
                v2 = fmaxf(v2, 0.f); v3 = fmaxf(v3, 0.f);
            }
            C[(size_t)row * N + col]           = v0;
            C[(size_t)row * N + col + 1]       = v1;
            C[(size_t)(row + 8) * N + col]     = v2;
            C[(size_t)(row + 8) * N + col + 1] = v3;
        }
    }
}

// ---------------------------------------------------------------------------
// Flash attention with TF32 mma.sync tensor cores.  (R6 version — proven.)
// Block = one (b,h) x 64 q rows. 4 warps (128 thr); 3 blocks/SM.
// Q fragments in registers; K/V double-buffered; P via shfl remap.
// ---------------------------------------------------------------------------
#define FAS 68
#define FA_TILE (64*FAS)
struct FlashSmem {
    float Ks[2][FA_TILE];
    float Vs[2][FA_TILE];
};
#define FLASH_SMEM_BYTES ((int)sizeof(FlashSmem))   // 69632 B -> 3 blocks/SM

__global__ __launch_bounds__(128)
void flash_attn_mma(const float* __restrict__ Q, const float* __restrict__ K,
                    const float* __restrict__ V, float* __restrict__ O, int causal)
{
    extern __shared__ char smem_raw[];
    FlashSmem& sm = *reinterpret_cast<FlashSmem*>(smem_raw);

    const int q0 = blockIdx.x * 64;
    const int bh = blockIdx.y;
    const int b = bh >> 4;
    const int h = bh & 15;

    const int tid  = threadIdx.x;
    const int lane = tid & 31;
    const int w    = tid >> 5;       // warp 0..3
    const int g    = lane >> 2;      // 0..7
    const int q    = lane & 3;       // 0..3

    // ---- Q fragments in registers (scale 1/8 folded, raw bits) ----
    uint32_t qf[8][4];
    {
        const float* Qb = Q + ((size_t)(b * Sc + q0 + w * 16) * Dc) + h * DKc;
#pragma unroll
        for (int ks = 0; ks < 8; ks++) {
            const int kc = ks * 8 + q;
            qf[ks][0] = __float_as_uint(0.125f * Qb[(size_t)g * Dc + kc]);
            qf[ks][1] = __float_as_uint(0.125f * Qb[(size_t)(g + 8) * Dc + kc]);
            qf[ks][2] = __float_as_uint(0.125f * Qb[(size_t)g * Dc + kc + 4]);
            qf[ks][3] = __float_as_uint(0.125f * Qb[(size_t)(g + 8) * Dc + kc + 4]);
        }
    }

    float o[8][4];
#pragma unroll
    for (int nt = 0; nt < 8; nt++)
#pragma unroll
        for (int r = 0; r < 4; r++) o[nt][r] = 0.f;
    float m0 = -1e30f, m1 = -1e30f, l0 = 0.f, l1 = 0.f;

    const int row0 = q0 + w * 16 + g;       // global q row for c0/c1
    const int row1 = row0 + 8;              // for c2/c3

    auto load_kv = [&](int t, int buf) {
        const float* Kg = K + ((size_t)(b * Sc + t * 64) * Dc) + h * DKc;
        const float* Vg = V + ((size_t)(b * Sc + t * 64) * Dc) + h * DKc;
        float* Kd = sm.Ks[buf];
        float* Vd = sm.Vs[buf];
#pragma unroll
        for (int i = 0; i < 8; i++) {
            int idx = tid + i * 128;        // 0..1023
            int row = idx >> 4, c4 = idx & 15;
            cp16(Kd + row * FAS + c4 * 4, Kg + (size_t)row * Dc + c4 * 4);
            cp16(Vd + row * FAS + c4 * 4, Vg + (size_t)row * Dc + c4 * 4);
        }
    };

    const int ntiles = causal ? (q0 / 64 + 1) : (Sc / 64);
    load_kv(0, 0);
    asm volatile("cp.async.commit_group;" ::: "memory");

    // shfl source lanes for the P (C-frag -> A-frag) remap
    const int srcA = (lane & ~3) | (q >> 1);
    const int srcB = srcA + 2;
    const bool oddq = (q & 1);

    for (int t = 0; t < ntiles; t++) {
        asm volatile("cp.async.wait_group 0;" ::: "memory");
        __syncthreads();
        if (t + 1 < ntiles) {
            load_kv(t + 1, (t + 1) & 1);
            asm volatile("cp.async.commit_group;" ::: "memory");
        }
        const float* Kb = sm.Ks[t & 1];
        const float* Vb = sm.Vs[t & 1];
        const int k0 = t * 64;

        // ---- S = Q @ K^T ----
        float s[8][4];
#pragma unroll
        for (int nt = 0; nt < 8; nt++)
#pragma unroll
            for (int r = 0; r < 4; r++) s[nt][r] = 0.f;

#pragma unroll
        for (int ks = 0; ks < 8; ks++) {
            const int kc = ks * 8 + q;
#pragma unroll
            for (int nt = 0; nt < 8; nt++) {
                const uint32_t* kr = (const uint32_t*)(Kb + (nt * 8 + g) * FAS + kc);
                MMA_TF32(s[nt], qf[ks][0], qf[ks][1], qf[ks][2], qf[ks][3],
                         kr[0], kr[4]);
            }
        }

        // ---- causal mask on diagonal tile ----
        if (causal && k0 == q0) {
#pragma unroll
            for (int nt = 0; nt < 8; nt++) {
                const int c = k0 + nt * 8 + 2 * q;
                if (c     > row0) s[nt][0] = -1e30f;
                if (c + 1 > row0) s[nt][1] = -1e30f;
                if (c     > row1) s[nt][2] = -1e30f;
                if (c + 1 > row1) s[nt][3] = -1e30f;
            }
        }

        // ---- online softmax (per-row state in registers) ----
        float t0 = -1e30f, t1 = -1e30f;
#pragma unroll
        for (int nt = 0; nt < 8; nt++) {
            t0 = fmaxf(t0, fmaxf(s[nt][0], s[nt][1]));
            t1 = fmaxf(t1, fmaxf(s[nt][2], s[nt][3]));
        }
        t0 = fmaxf(t0, __shfl_xor_sync(0xffffffffu, t0, 1));
        t0 = fmaxf(t0, __shfl_xor_sync(0xffffffffu, t0, 2));
        t1 = fmaxf(t1, __shfl_xor_sync(0xffffffffu, t1, 1));
        t1 = fmaxf(t1, __shfl_xor_sync(0xffffffffu, t1, 2));
        const float mn0 = fmaxf(m0, t0);
        const float mn1 = fmaxf(m1, t1);
        const float a0 = __expf(m0 - mn0);
        const float a1 = __expf(m1 - mn1);

        float sum0 = 0.f, sum1 = 0.f;
#pragma unroll
        for (int nt = 0; nt < 8; nt++) {
            float p0 = __expf(s[nt][0] - mn0);
            float p1 = __expf(s[nt][1] - mn0);
            float p2 = __expf(s[nt][2] - mn1);
            float p3 = __expf(s[nt][3] - mn1);
            s[nt][0] = p0; s[nt][1] = p1; s[nt][2] = p2; s[nt][3] = p3;
            sum0 += p0 + p1;
            sum1 += p2 + p3;
        }
        sum0 += __shfl_xor_sync(0xffffffffu, sum0, 1);
        sum0 += __shfl_xor_sync(0xffffffffu, sum0, 2);
        sum1 += __shfl_xor_sync(0xffffffffu, sum1, 1);
        sum1 += __shfl_xor_sync(0xffffffffu, sum1, 2);
        l0 = l0 * a0 + sum0;
        l1 = l1 * a1 + sum1;
        m0 = mn0; m1 = mn1;

#pragma unroll
        for (int nt = 0; nt < 8; nt++) {
            o[nt][0] *= a0; o[nt][1] *= a0;
            o[nt][2] *= a1; o[nt][3] *= a1;
        }

        // ---- O += P @ V  (P A-fragments built via shfl from C-fragments) ----
#pragma unroll
        for (int ks = 0; ks < 8; ks++) {
            float e0A = __shfl_sync(0xffffffffu, s[ks][0], srcA);
            float e1A = __shfl_sync(0xffffffffu, s[ks][1], srcA);
            float e2A = __shfl_sync(0xffffffffu, s[ks][2], srcA);
            float e3A = __shfl_sync(0xffffffffu, s[ks][3], srcA);
            float e0B = __shfl_sync(0xffffffffu, s[ks][0], srcB);
            float e1B = __shfl_sync(0xffffffffu, s[ks][1], srcB);
            float e2B = __shfl_sync(0xffffffffu, s[ks][2], srcB);
            float e3B = __shfl_sync(0xffffffffu, s[ks][3], srcB);
            uint32_t pa0 = __float_as_uint(oddq ? e1A : e0A);
            uint32_t pa1 = __float_as_uint(oddq ? e3A : e2A);
            uint32_t pa2 = __float_as_uint(oddq ? e1B : e0B);
            uint32_t pa3 = __float_as_uint(oddq ? e3B : e2B);

            const int kc = ks * 8 + q;
#pragma unroll
            for (int nt = 0; nt < 8; nt++) {
                const uint32_t* vr = (const uint32_t*)(Vb + kc * FAS + nt * 8 + g);
                MMA_TF32(o[nt], pa0, pa1, pa2, pa3, vr[0], vr[4 * FAS]);
            }
        }
        __syncthreads();
    }

    // ---- write O ----
    const float invl0 = 1.f / l0;
    const float invl1 = 1.f / l1;
    float* Ob0 = O + ((size_t)(b * Sc + row0) * Dc) + h * DKc;
    float* Ob1 = O + ((size_t)(b * Sc + row1) * Dc) + h * DKc;
#pragma unroll
    for (int nt = 0; nt < 8; nt++) {
        const int c = nt * 8 + 2 * q;
        *(float2*)&Ob0[c] = make_float2(o[nt][0] * invl0, o[nt][1] * invl0);
        *(float2*)&Ob1[c] = make_float2(o[nt][2] * invl1, o[nt][3] * invl1);
    }
}

// ---------------------------------------------------------------------------
// y = a + b, then normalize over the SEQUENCE dim: (y - mean) / unbiased_var
// Fused single kernel; block = 8 cols x 128 seq-threads, grid (128, 2) = 256
// blocks (vs 64 before) -> full chip. Warp = 4 rows x 8 contiguous floats
// (4x32B aligned sectors per 128B useful -> same coalescing efficiency).
// 3-stage fixed-order reduction (128 -> 8 -> 1) for determinism.
// ---------------------------------------------------------------------------
__global__ __launch_bounds__(1024)
void add_seqnorm(const float* __restrict__ a, const float* __restrict__ b,
                 float* __restrict__ out)
{
    const int tx = threadIdx.x;          // 0..7   (d within block)
    const int ty = threadIdx.y;          // 0..127 (seq stride)
    const int d  = blockIdx.x * 8 + tx;
    const int bb = blockIdx.y;
    const size_t base = (size_t)bb * Sc * Dc + d;

    float sum = 0.f, sq = 0.f;
    for (int s = ty; s < Sc; s += 128) {     // 16 iterations
        size_t off = base + (size_t)s * Dc;
        float y = a[off] + b[off];
        out[off] = y;
        sum += y;
        sq  += y * y;
    }

    __shared__ float ssum[128][9], ssq[128][9];
    ssum[ty][tx] = sum;
    ssq[ty][tx]  = sq;
    __syncthreads();

    __shared__ float s2[8][9], q2[8][9];
    if (ty < 8) {
        float S = 0.f, Q = 0.f;
#pragma unroll
        for (int i = 0; i < 16; i++) {
            S += ssum[ty + i * 8][tx];
            Q += ssq[ty + i * 8][tx];
        }
        s2[ty][tx] = S;
        q2[ty][tx] = Q;
    }
    __syncthreads();

    __shared__ float smean[8], sinv[8];
    if (ty == 0) {
        float S = 0.f, Q = 0.f;
#pragma unroll
        for (int i = 0; i < 8; i++) { S += s2[i][tx]; Q += q2[i][tx]; }
        float m   = S / (float)Sc;
        float var = (Q - (float)Sc * m * m) / (float)(Sc - 1);
        smean[tx] = m;
        sinv[tx]  = 1.f / var;
    }
    __syncthreads();

    const float m   = smean[tx];
    const float inv = sinv[tx];
    for (int s = ty; s < Sc; s += 128) {
        size_t off = base + (size_t)s * Dc;
        out[off] = (out[off] - m) * inv;
    }
}

// ---------------------------------------------------------------------------
// Launch
// ---------------------------------------------------------------------------
extern "C" void kernel_launch(void* const* d_in, const int* in_sizes, int n_in,
                              void* d_out, int out_size)
{
    const float* dec = (const float*)d_in[0];
    const float* enc = (const float*)d_in[1];
    const float* Wq1 = (const float*)d_in[2];
    const float* Wk1 = (const float*)d_in[3];
    const float* Wv1 = (const float*)d_in[4];
    const float* bq1 = (const float*)d_in[5];
    const float* bk1 = (const float*)d_in[6];
    const float* bv1 = (const float*)d_in[7];
    const float* Wq2 = (const float*)d_in[8];
    const float* Wk2 = (const float*)d_in[9];
    const float* Wv2 = (const float*)d_in[10];
    const float* bq2 = (const float*)d_in[11];
    const float* bk2 = (const float*)d_in[12];
    const float* bv2 = (const float*)d_in[13];
    const float* W1  = (const float*)d_in[14];
    const float* b1  = (const float*)d_in[15];
    const float* W2  = (const float*)d_in[16];
    const float* b2  = (const float*)d_in[17];
    float* out = (float*)d_out;

    float *q, *k, *v, *t, *x1, *x2, *hbuf;
    cudaGetSymbolAddress((void**)&q,    g_q);
    cudaGetSymbolAddress((void**)&k,    g_k);
    cudaGetSymbolAddress((void**)&v,    g_v);
    cudaGetSymbolAddress((void**)&t,    g_t);
    cudaGetSymbolAddress((void**)&x1,   g_x1);
    cudaGetSymbolAddress((void**)&x2,   g_x2);
    cudaGetSymbolAddress((void**)&hbuf, g_h);

    static bool attr_set = false;
    if (!attr_set) {
        cudaFuncSetAttribute(flash_attn_mma, cudaFuncAttributeMaxDynamicSharedMemorySize,
                             FLASH_SMEM_BYTES);
        cudaFuncSetAttribute(gemm_tf32, cudaFuncAttributeMaxDynamicSharedMemorySize,
                             GEMM_SMEM_BYTES);
        attr_set = true;
    }

    dim3 gemm_block(256);
    dim3 gproj(Dc / 128, ROWS / 128);     // (8, 32)
    dim3 gff1(FFc / 128, ROWS / 128);     // (32, 32)
    dim3 gff2(Dc / 128, ROWS / 128);

    dim3 fgrid(Sc / 64, Bc * Hc);         // (32, 32)
    dim3 fblock(128);

    dim3 ngrid(Dc / 8, Bc);               // (128, 2) = 256 blocks
    dim3 nblock(8, 128);

    // ---- sublayer 1: causal self-attention ----
    gemm_tf32<<<gproj, gemm_block, GEMM_SMEM_BYTES>>>(dec, Wq1, bq1, q, ROWS, Dc, Dc, 0);
    gemm_tf32<<<gproj, gemm_block, GEMM_SMEM_BYTES>>>(dec, Wk1, bk1, k, ROWS, Dc, Dc, 0);
    gemm_tf32<<<gproj, gemm_block, GEMM_SMEM_BYTES>>>(dec, Wv1, bv1, v, ROWS, Dc, Dc, 0);
    flash_attn_mma<<<fgrid, fblock, FLASH_SMEM_BYTES>>>(q, k, v, t, 1);
    add_seqnorm<<<ngrid, nblock>>>(t, dec, x1);

    // ---- sublayer 2: cross-attention ----
    gemm_tf32<<<gproj, gemm_block, GEMM_SMEM_BYTES>>>(x1,  Wq2, bq2, q, ROWS, Dc, Dc, 0);
    gemm_tf32<<<gproj, gemm_block, GEMM_SMEM_BYTES>>>(enc, Wk2, bk2, k, ROWS, Dc, Dc, 0);
    gemm_tf32<<<gproj, gemm_block, GEMM_SMEM_BYTES>>>(enc, Wv2, bv2, v, ROWS, Dc, Dc, 0);
    flash_attn_mma<<<fgrid, fblock, FLASH_SMEM_BYTES>>>(q, k, v, t, 0);
    add_seqnorm<<<ngrid, nblock>>>(t, x1, x2);

    // ---- sublayer 3: FFN ----
    gemm_tf32<<<gff1, gemm_block, GEMM_SMEM_BYTES>>>(x2, W1, b1, hbuf, ROWS, FFc, Dc, 1);
    gemm_tf32<<<gff2, gemm_block, GEMM_SMEM_BYTES>>>(hbuf, W2, b2, t, ROWS, Dc, FFc, 0);
    add_seqnorm<<<ngrid, nblock>>>(t, x2, out);
}

// round 13
// speedup vs baseline: 1.1918x; 1.1167x over previous
#include <cuda_runtime.h>
#include <cuda_fp16.h>
#include <cstddef>
#include <cstdint>

// Problem constants
#define Bc 2
#define Sc 2048
#define Dc 1024
#define Hc 16
#define DKc 64
#define FFc 4096
#define ROWS (Bc*Sc)          // 4096 flattened rows

// ---------------------------------------------------------------------------
// Scratch (static device allocations; no cudaMalloc allowed)
// ---------------------------------------------------------------------------
__device__ float g_q[ROWS*Dc];
__device__ float g_k[ROWS*Dc];
__device__ float g_v[ROWS*Dc];
__device__ float g_t[ROWS*Dc];    // attention out / ffn out
__device__ float g_x1[ROWS*Dc];
__device__ float g_x2[ROWS*Dc];
__device__ float g_h[ROWS*FFc];   // ffn hidden (fp32)
// half-precision staging
__device__ __half h_dec[ROWS*Dc];
__device__ __half h_enc[ROWS*Dc];
__device__ __half h_x[ROWS*Dc];     // x1_h then x2_h (sequential reuse)
__device__ __half h_hid[ROWS*FFc];
__device__ __half h_w[14*1024*1024]; // transposed half weights

__device__ __forceinline__ void cp16(void* s, const void* g) {
    uint32_t sa = (uint32_t)__cvta_generic_to_shared(s);
    asm volatile("cp.async.cg.shared.global [%0], [%1], 16;" :: "r"(sa), "l"(g));
}
// tf32 "fast path" mma (flash attention)
#define MMA_TF32(C, A0,A1,A2,A3, B0,B1)                                    \
    asm volatile(                                                          \
        "mma.sync.aligned.m16n8k8.row.col.f32.tf32.tf32.f32 "              \
        "{%0,%1,%2,%3}, {%4,%5,%6,%7}, {%8,%9}, {%0,%1,%2,%3};"            \
        : "+f"((C)[0]), "+f"((C)[1]), "+f"((C)[2]), "+f"((C)[3])           \
        : "r"(A0), "r"(A1), "r"(A2), "r"(A3), "r"(B0), "r"(B1))
// fp16 k16 mma (GEMM)
#define MMA_F16(C, A0,A1,A2,A3, B0,B1)                                     \
    asm volatile(                                                          \
        "mma.sync.aligned.m16n8k16.row.col.f32.f16.f16.f32 "               \
        "{%0,%1,%2,%3}, {%4,%5,%6,%7}, {%8,%9}, {%0,%1,%2,%3};"            \
        : "+f"((C)[0]), "+f"((C)[1]), "+f"((C)[2]), "+f"((C)[3])           \
        : "r"(A0), "r"(A1), "r"(A2), "r"(A3), "r"(B0), "r"(B1))

// ---------------------------------------------------------------------------
// fp32 -> fp16 elementwise convert (n % 4 == 0)
// ---------------------------------------------------------------------------
__global__ __launch_bounds__(256)
void cvt_half(const float* __restrict__ in, __half* __restrict__ out, int n)
{
    int i = (blockIdx.x * 256 + threadIdx.x) * 4;
    if (i < n) {
        float4 v = *(const float4*)(in + i);
        *(__half2*)(out + i)     = __floats2half2_rn(v.x, v.y);
        *(__half2*)(out + i + 2) = __floats2half2_rn(v.z, v.w);
    }
}

// ---------------------------------------------------------------------------
// Weight transpose + convert: Wt[n][k] = (half)W[k][n]
// ---------------------------------------------------------------------------
__global__ __launch_bounds__(1024)
void transpose_cvt(const float* __restrict__ W, __half* __restrict__ Wt,
                   int K, int N)
{
    __shared__ float tile[32][33];
    const int n0 = blockIdx.x * 32, k0 = blockIdx.y * 32;
    tile[threadIdx.y][threadIdx.x] = W[(size_t)(k0 + threadIdx.y) * N + n0 + threadIdx.x];
    __syncthreads();
    Wt[(size_t)(n0 + threadIdx.y) * K + k0 + threadIdx.x] =
        __float2half(tile[threadIdx.x][threadIdx.y]);
}

// ---------------------------------------------------------------------------
// FP16 tensor-core GEMM: C[M,N] = A[M,K](half) @ Bt[N,K](half)^T + bias, ReLU opt.
// Block tile 128x128, BK=32, 256 threads (8 warps 2x4), warp tile 64x32.
// m16n8k16: per 32-k chunk only 32 MMA + 48 LDS (vs 64+96 for tf32 k8).
// Smem stride 40 halves -> all fragment loads conflict-free.
// ---------------------------------------------------------------------------
#define HS 40
#define HT (128*HS)   // 5120 halves per buffer

__global__ __launch_bounds__(256)
void gemm_f16(const __half* __restrict__ A, const __half* __restrict__ Bt,
              const float* __restrict__ bias, float* __restrict__ C,
              int M, int N, int K, int relu)
{
    __shared__ __align__(16) __half As[2*HT];
    __shared__ __align__(16) __half Bs[2*HT];

    const int tid  = threadIdx.x;
    const int lane = tid & 31;
    const int wid  = tid >> 5;
    const int wm   = wid >> 2;
    const int wn   = wid & 3;
    const int grp  = lane >> 2;
    const int qid  = lane & 3;
    const int bm   = blockIdx.y * 128;
    const int bn   = blockIdx.x * 128;

    float c[4][4][4];
#pragma unroll
    for (int mt = 0; mt < 4; mt++)
#pragma unroll
        for (int nt = 0; nt < 4; nt++)
#pragma unroll
            for (int r = 0; r < 4; r++) c[mt][nt][r] = 0.f;

    const int T = K / 32;

    auto load_tile = [&](int t, int buf) {
        const __half* Ag = A  + (size_t)bm * K + t * 32;
        const __half* Bg = Bt + (size_t)bn * K + t * 32;
        __half* Ad = As + buf * HT;
        __half* Bd = Bs + buf * HT;
#pragma unroll
        for (int i = 0; i < 2; i++) {
            int idx = tid + i * 256;          // 0..511
            int row = idx >> 2, c8 = idx & 3; // 128 rows x 4 chunks of 8 halves
            cp16(Ad + row * HS + c8 * 8, Ag + (size_t)row * K + c8 * 8);
            cp16(Bd + row * HS + c8 * 8, Bg + (size_t)row * K + c8 * 8);
        }
    };

    load_tile(0, 0);
    asm volatile("cp.async.commit_group;" ::: "memory");

    for (int t = 0; t < T; t++) {
        asm volatile("cp.async.wait_group 0;" ::: "memory");
        __syncthreads();
        if (t + 1 < T) {
            load_tile(t + 1, (t + 1) & 1);
            asm volatile("cp.async.commit_group;" ::: "memory");
        }
        const __half* Ab = As + (t & 1) * HT;
        const __half* Bb = Bs + (t & 1) * HT;

#pragma unroll
        for (int ks = 0; ks < 2; ks++) {
            const int kb = ks * 16;
            uint32_t af[4][4], bf[4][2];
#pragma unroll
            for (int mt = 0; mt < 4; mt++) {
                const int row0 = wm * 64 + mt * 16 + grp;
                af[mt][0] = *(const uint32_t*)(Ab + row0 * HS + kb + 2 * qid);
                af[mt][1] = *(const uint32_t*)(Ab + (row0 + 8) * HS + kb + 2 * qid);
                af[mt][2] = *(const uint32_t*)(Ab + row0 * HS + kb + 2 * qid + 8);
                af[mt][3] = *(const uint32_t*)(Ab + (row0 + 8) * HS + kb + 2 * qid + 8);
            }
#pragma unroll
            for (int nt = 0; nt < 4; nt++) {
                const int n0 = wn * 32 + nt * 8 + grp;
                bf[nt][0] = *(const uint32_t*)(Bb + n0 * HS + kb + 2 * qid);
                bf[nt][1] = *(const uint32_t*)(Bb + n0 * HS + kb + 2 * qid + 8);
            }
#pragma unroll
            for (int mt = 0; mt < 4; mt++)
#pragma unroll
                for (int nt = 0; nt < 4; nt++)
                    MMA_F16(c[mt][nt], af[mt][0], af[mt][1], af[mt][2], af[mt][3],
                            bf[nt][0], bf[nt][1]);
        }
        __syncthreads();
    }

#pragma unroll
    for (int mt = 0; mt < 4; mt++) {
        const int row = bm + wm * 64 + mt * 16 + grp;
#pragma unroll
        for (int nt = 0; nt < 4; nt++) {
            const int col = bn + wn * 32 + nt * 8 + qid * 2;
            const float b0 = bias[col], b1 = bias[col + 1];
            float v0 = c[mt][nt][0] + b0;
            float v1 = c[mt][nt][1] + b1;
            float v2 = c[mt][nt][2] + b0;
            float v3 = c[mt][nt][3] + b1;
            if (relu) {
                v0 = fmaxf(v0, 0.f); v1 = fmaxf(v1, 0.f);
                v2 = fmaxf(v2, 0.f); v3 = fmaxf(v3, 0.f);
            }
            C[(size_t)row * N + col]           = v0;
            C[(size_t)row * N + col + 1]       = v1;
            C[(size_t)(row + 8) * N + col]     = v2;
            C[(size_t)(row + 8) * N + col + 1] = v3;
        }
    }
}

// ---------------------------------------------------------------------------
// Flash attention with TF32 mma.sync tensor cores.  (R6/R11 version — proven.)
// ---------------------------------------------------------------------------
#define FAS 68
#define FA_TILE (64*FAS)
struct FlashSmem {
    float Ks[2][FA_TILE];
    float Vs[2][FA_TILE];
};
#define FLASH_SMEM_BYTES ((int)sizeof(FlashSmem))   // 69632 B -> 3 blocks/SM

__global__ __launch_bounds__(128)
void flash_attn_mma(const float* __restrict__ Q, const float* __restrict__ K,
                    const float* __restrict__ V, float* __restrict__ O, int causal)
{
    extern __shared__ char smem_raw[];
    FlashSmem& sm = *reinterpret_cast<FlashSmem*>(smem_raw);

    const int q0 = blockIdx.x * 64;
    const int bh = blockIdx.y;
    const int b = bh >> 4;
    const int h = bh & 15;

    const int tid  = threadIdx.x;
    const int lane = tid & 31;
    const int w    = tid >> 5;
    const int g    = lane >> 2;
    const int q    = lane & 3;

    uint32_t qf[8][4];
    {
        const float* Qb = Q + ((size_t)(b * Sc + q0 + w * 16) * Dc) + h * DKc;
#pragma unroll
        for (int ks = 0; ks < 8; ks++) {
            const int kc = ks * 8 + q;
            qf[ks][0] = __float_as_uint(0.125f * Qb[(size_t)g * Dc + kc]);
            qf[ks][1] = __float_as_uint(0.125f * Qb[(size_t)(g + 8) * Dc + kc]);
            qf[ks][2] = __float_as_uint(0.125f * Qb[(size_t)g * Dc + kc + 4]);
            qf[ks][3] = __float_as_uint(0.125f * Qb[(size_t)(g + 8) * Dc + kc + 4]);
        }
    }

    float o[8][4];
#pragma unroll
    for (int nt = 0; nt < 8; nt++)
#pragma unroll
        for (int r = 0; r < 4; r++) o[nt][r] = 0.f;
    float m0 = -1e30f, m1 = -1e30f, l0 = 0.f, l1 = 0.f;

    const int row0 = q0 + w * 16 + g;
    const int row1 = row0 + 8;

    auto load_kv = [&](int t, int buf) {
        const float* Kg = K + ((size_t)(b * Sc + t * 64) * Dc) + h * DKc;
        const float* Vg = V + ((size_t)(b * Sc + t * 64) * Dc) + h * DKc;
        float* Kd = sm.Ks[buf];
        float* Vd = sm.Vs[buf];
#pragma unroll
        for (int i = 0; i < 8; i++) {
            int idx = tid + i * 128;
            int row = idx >> 4, c4 = idx & 15;
            cp16(Kd + row * FAS + c4 * 4, Kg + (size_t)row * Dc + c4 * 4);
            cp16(Vd + row * FAS + c4 * 4, Vg + (size_t)row * Dc + c4 * 4);
        }
    };

    const int ntiles = causal ? (q0 / 64 + 1) : (Sc / 64);
    load_kv(0, 0);
    asm volatile("cp.async.commit_group;" ::: "memory");

    const int srcA = (lane & ~3) | (q >> 1);
    const int srcB = srcA + 2;
    const bool oddq = (q & 1);

    for (int t = 0; t < ntiles; t++) {
        asm volatile("cp.async.wait_group 0;" ::: "memory");
        __syncthreads();
        if (t + 1 < ntiles) {
            load_kv(t + 1, (t + 1) & 1);
            asm volatile("cp.async.commit_group;" ::: "memory");
        }
        const float* Kb = sm.Ks[t & 1];
        const float* Vb = sm.Vs[t & 1];
        const int k0 = t * 64;

        float s[8][4];
#pragma unroll
        for (int nt = 0; nt < 8; nt++)
#pragma unroll
            for (int r = 0; r < 4; r++) s[nt][r] = 0.f;

#pragma unroll
        for (int ks = 0; ks < 8; ks++) {
            const int kc = ks * 8 + q;
#pragma unroll
            for (int nt = 0; nt < 8; nt++) {
                const uint32_t* kr = (const uint32_t*)(Kb + (nt * 8 + g) * FAS + kc);
                MMA_TF32(s[nt], qf[ks][0], qf[ks][1], qf[ks][2], qf[ks][3],
                         kr[0], kr[4]);
            }
        }

        if (causal && k0 == q0) {
#pragma unroll
            for (int nt = 0; nt < 8; nt++) {
                const int c = k0 + nt * 8 + 2 * q;
                if (c     > row0) s[nt][0] = -1e30f;
                if (c + 1 > row0) s[nt][1] = -1e30f;
                if (c     > row1) s[nt][2] = -1e30f;
                if (c + 1 > row1) s[nt][3] = -1e30f;
            }
        }

        float t0 = -1e30f, t1 = -1e30f;
#pragma unroll
        for (int nt = 0; nt < 8; nt++) {
            t0 = fmaxf(t0, fmaxf(s[nt][0], s[nt][1]));
            t1 = fmaxf(t1, fmaxf(s[nt][2], s[nt][3]));
        }
        t0 = fmaxf(t0, __shfl_xor_sync(0xffffffffu, t0, 1));
        t0 = fmaxf(t0, __shfl_xor_sync(0xffffffffu, t0, 2));
        t1 = fmaxf(t1, __shfl_xor_sync(0xffffffffu, t1, 1));
        t1 = fmaxf(t1, __shfl_xor_sync(0xffffffffu, t1, 2));
        const float mn0 = fmaxf(m0, t0);
        const float mn1 = fmaxf(m1, t1);
        const float a0 = __expf(m0 - mn0);
        const float a1 = __expf(m1 - mn1);

        float sum0 = 0.f, sum1 = 0.f;
#pragma unroll
        for (int nt = 0; nt < 8; nt++) {
            float p0 = __expf(s[nt][0] - mn0);
            float p1 = __expf(s[nt][1] - mn0);
            float p2 = __expf(s[nt][2] - mn1);
            float p3 = __expf(s[nt][3] - mn1);
            s[nt][0] = p0; s[nt][1] = p1; s[nt][2] = p2; s[nt][3] = p3;
            sum0 += p0 + p1;
            sum1 += p2 + p3;
        }
        sum0 += __shfl_xor_sync(0xffffffffu, sum0, 1);
        sum0 += __shfl_xor_sync(0xffffffffu, sum0, 2);
        sum1 += __shfl_xor_sync(0xffffffffu, sum1, 1);
        sum1 += __shfl_xor_sync(0xffffffffu, sum1, 2);
        l0 = l0 * a0 + sum0;
        l1 = l1 * a1 + sum1;
        m0 = mn0; m1 = mn1;

#pragma unroll
        for (int nt = 0; nt < 8; nt++) {
            o[nt][0] *= a0; o[nt][1] *= a0;
            o[nt][2] *= a1; o[nt][3] *= a1;
        }

#pragma unroll
        for (int ks = 0; ks < 8; ks++) {
            float e0A = __shfl_sync(0xffffffffu, s[ks][0], srcA);
            float e1A = __shfl_sync(0xffffffffu, s[ks][1], srcA);
            float e2A = __shfl_sync(0xffffffffu, s[ks][2], srcA);
            float e3A = __shfl_sync(0xffffffffu, s[ks][3], srcA);
            float e0B = __shfl_sync(0xffffffffu, s[ks][0], srcB);
            float e1B = __shfl_sync(0xffffffffu, s[ks][1], srcB);
            float e2B = __shfl_sync(0xffffffffu, s[ks][2], srcB);
            float e3B = __shfl_sync(0xffffffffu, s[ks][3], srcB);
            uint32_t pa0 = __float_as_uint(oddq ? e1A : e0A);
            uint32_t pa1 = __float_as_uint(oddq ? e3A : e2A);
            uint32_t pa2 = __float_as_uint(oddq ? e1B : e0B);
            uint32_t pa3 = __float_as_uint(oddq ? e3B : e2B);

            const int kc = ks * 8 + q;
#pragma unroll
            for (int nt = 0; nt < 8; nt++) {
                const uint32_t* vr = (const uint32_t*)(Vb + kc * FAS + nt * 8 + g);
                MMA_TF32(o[nt], pa0, pa1, pa2, pa3, vr[0], vr[4 * FAS]);
            }
        }
        __syncthreads();
    }

    const float invl0 = 1.f / l0;
    const float invl1 = 1.f / l1;
    float* Ob0 = O + ((size_t)(b * Sc + row0) * Dc) + h * DKc;
    float* Ob1 = O + ((size_t)(b * Sc + row1) * Dc) + h * DKc;
#pragma unroll
    for (int nt = 0; nt < 8; nt++) {
        const int c = nt * 8 + 2 * q;
        *(float2*)&Ob0[c] = make_float2(o[nt][0] * invl0, o[nt][1] * invl0);
        *(float2*)&Ob1[c] = make_float2(o[nt][2] * invl1, o[nt][3] * invl1);
    }
}

// ---------------------------------------------------------------------------
// y = a + b, then normalize over the SEQUENCE dim. (R11 version.)
// ---------------------------------------------------------------------------
__global__ __launch_bounds__(1024)
void add_seqnorm(const float* __restrict__ a, const float* __restrict__ b,
                 float* __restrict__ out)
{
    const int tx = threadIdx.x;
    const int ty = threadIdx.y;
    const int d  = blockIdx.x * 8 + tx;
    const int bb = blockIdx.y;
    const size_t base = (size_t)bb * Sc * Dc + d;

    float sum = 0.f, sq = 0.f;
    for (int s = ty; s < Sc; s += 128) {
        size_t off = base + (size_t)s * Dc;
        float y = a[off] + b[off];
        out[off] = y;
        sum += y;
        sq  += y * y;
    }

    __shared__ float ssum[128][9], ssq[128][9];
    ssum[ty][tx] = sum;
    ssq[ty][tx]  = sq;
    __syncthreads();

    __shared__ float s2[8][9], q2[8][9];
    if (ty < 8) {
        float S = 0.f, Q = 0.f;
#pragma unroll
        for (int i = 0; i < 16; i++) {
            S += ssum[ty + i * 8][tx];
            Q += ssq[ty + i * 8][tx];
        }
        s2[ty][tx] = S;
        q2[ty][tx] = Q;
    }
    __syncthreads();

    __shared__ float smean[8], sinv[8];
    if (ty == 0) {
        float S = 0.f, Q = 0.f;
#pragma unroll
        for (int i = 0; i < 8; i++) { S += s2[i][tx]; Q += q2[i][tx]; }
        float m   = S / (float)Sc;
        float var = (Q - (float)Sc * m * m) / (float)(Sc - 1);
        smean[tx] = m;
        sinv[tx]  = 1.f / var;
    }
    __syncthreads();

    const float m   = smean[tx];
    const float inv = sinv[tx];
    for (int s = ty; s < Sc; s += 128) {
        size_t off = base + (size_t)s * Dc;
        out[off] = (out[off] - m) * inv;
    }
}

// ---------------------------------------------------------------------------
// Launch
// ---------------------------------------------------------------------------
extern "C" void kernel_launch(void* const* d_in, const int* in_sizes, int n_in,
                              void* d_out, int out_size)
{
    const float* dec = (const float*)d_in[0];
    const float* enc = (const float*)d_in[1];
    const float* Wq1 = (const float*)d_in[2];
    const float* Wk1 = (const float*)d_in[3];
    const float* Wv1 = (const float*)d_in[4];
    const float* bq1 = (const float*)d_in[5];
    const float* bk1 = (const float*)d_in[6];
    const float* bv1 = (const float*)d_in[7];
    const float* Wq2 = (const float*)d_in[8];
    const float* Wk2 = (const float*)d_in[9];
    const float* Wv2 = (const float*)d_in[10];
    const float* bq2 = (const float*)d_in[11];
    const float* bk2 = (const float*)d_in[12];
    const float* bv2 = (const float*)d_in[13];
    const float* W1  = (const float*)d_in[14];
    const float* b1  = (const float*)d_in[15];
    const float* W2  = (const float*)d_in[16];
    const float* b2  = (const float*)d_in[17];
    float* out = (float*)d_out;

    float *q, *k, *v, *t, *x1, *x2, *hbuf;
    __half *dech, *ench, *xh, *hidh, *wh;
    cudaGetSymbolAddress((void**)&q,    g_q);
    cudaGetSymbolAddress((void**)&k,    g_k);
    cudaGetSymbolAddress((void**)&v,    g_v);
    cudaGetSymbolAddress((void**)&t,    g_t);
    cudaGetSymbolAddress((void**)&x1,   g_x1);
    cudaGetSymbolAddress((void**)&x2,   g_x2);
    cudaGetSymbolAddress((void**)&hbuf, g_h);
    cudaGetSymbolAddress((void**)&dech, h_dec);
    cudaGetSymbolAddress((void**)&ench, h_enc);
    cudaGetSymbolAddress((void**)&xh,   h_x);
    cudaGetSymbolAddress((void**)&hidh, h_hid);
    cudaGetSymbolAddress((void**)&wh,   h_w);

    __half* wq1h = wh;
    __half* wk1h = wh + 1*1024*1024;
    __half* wv1h = wh + 2*1024*1024;
    __half* wq2h = wh + 3*1024*1024;
    __half* wk2h = wh + 4*1024*1024;
    __half* wv2h = wh + 5*1024*1024;
    __half* w1h  = wh + 6*1024*1024;   // [FFc][Dc]
    __half* w2h  = wh + 10*1024*1024;  // [Dc][FFc]

    static bool attr_set = false;
    if (!attr_set) {
        cudaFuncSetAttribute(flash_attn_mma, cudaFuncAttributeMaxDynamicSharedMemorySize,
                             FLASH_SMEM_BYTES);
        attr_set = true;
    }

    dim3 tblk(32, 32);
    dim3 tg_sq(Dc / 32, Dc / 32);
    dim3 tg_w1(FFc / 32, Dc / 32);     // W1: K=Dc rows, N=FFc cols
    dim3 tg_w2(Dc / 32, FFc / 32);     // W2: K=FFc rows, N=Dc cols

    const int NDC = ROWS * Dc;         // 4M elems
    const int NFF = ROWS * FFc;        // 16M elems
    dim3 cblk(256);
    dim3 cg_dc(NDC / 1024);
    dim3 cg_ff(NFF / 1024);

    dim3 gblk(256);
    dim3 gproj(Dc / 128, ROWS / 128);  // (8, 32)
    dim3 gff1(FFc / 128, ROWS / 128);  // (32, 32)
    dim3 gff2(Dc / 128, ROWS / 128);

    dim3 fgrid(Sc / 64, Bc * Hc);
    dim3 fblock(128);
    dim3 ngrid(Dc / 8, Bc);
    dim3 nblock(8, 128);

    // ---- weight transpose+convert & input conversions ----
    transpose_cvt<<<tg_sq, tblk>>>(Wq1, wq1h, Dc, Dc);
    transpose_cvt<<<tg_sq, tblk>>>(Wk1, wk1h, Dc, Dc);
    transpose_cvt<<<tg_sq, tblk>>>(Wv1, wv1h, Dc, Dc);
    transpose_cvt<<<tg_sq, tblk>>>(Wq2, wq2h, Dc, Dc);
    transpose_cvt<<<tg_sq, tblk>>>(Wk2, wk2h, Dc, Dc);
    transpose_cvt<<<tg_sq, tblk>>>(Wv2, wv2h, Dc, Dc);
    transpose_cvt<<<tg_w1, tblk>>>(W1, w1h, Dc, FFc);
    transpose_cvt<<<tg_w2, tblk>>>(W2, w2h, FFc, Dc);
    cvt_half<<<cg_dc, cblk>>>(dec, dech, NDC);
    cvt_half<<<cg_dc, cblk>>>(enc, ench, NDC);

    // ---- sublayer 1: causal self-attention ----
    gemm_f16<<<gproj, gblk>>>(dech, wq1h, bq1, q, ROWS, Dc, Dc, 0);
    gemm_f16<<<gproj, gblk>>>(dech, wk1h, bk1, k, ROWS, Dc, Dc, 0);
    gemm_f16<<<gproj, gblk>>>(dech, wv1h, bv1, v, ROWS, Dc, Dc, 0);
    flash_attn_mma<<<fgrid, fblock, FLASH_SMEM_BYTES>>>(q, k, v, t, 1);
    add_seqnorm<<<ngrid, nblock>>>(t, dec, x1);

    // ---- sublayer 2: cross-attention ----
    cvt_half<<<cg_dc, cblk>>>(x1, xh, NDC);
    gemm_f16<<<gproj, gblk>>>(xh,   wq2h, bq2, q, ROWS, Dc, Dc, 0);
    gemm_f16<<<gproj, gblk>>>(ench, wk2h, bk2, k, ROWS, Dc, Dc, 0);
    gemm_f16<<<gproj, gblk>>>(ench, wv2h, bv2, v, ROWS, Dc, Dc, 0);
    flash_attn_mma<<<fgrid, fblock, FLASH_SMEM_BYTES>>>(q, k, v, t, 0);
    add_seqnorm<<<ngrid, nblock>>>(t, x1, x2);

    // ---- sublayer 3: FFN ----
    cvt_half<<<cg_dc, cblk>>>(x2, xh, NDC);
    gemm_f16<<<gff1, gblk>>>(xh, w1h, b1, hbuf, ROWS, FFc, Dc, 1);
    cvt_half<<<cg_ff, cblk>>>(hbuf, hidh, NFF);
    gemm_f16<<<gff2, gblk>>>(hidh, w2h, b2, t, ROWS, Dc, FFc, 0);
    add_seqnorm<<<ngrid, nblock>>>(t, x2, out);
}